// round 1
// baseline (speedup 1.0000x reference)
#include <cuda_runtime.h>
#include <math.h>

#define BATCH 2048
#define T 50
#define D 256
#define NEGC (-100000.0f)
#define INV_SQRT_D 0.0625f

// ---------------- device scratch (no allocations allowed) ----------------
__device__ float g_Abig[D * D];          // Wq^T @ Wk
__device__ float g_u[D];                 // Wq^T bk
__device__ float g_wv[D];                // Wk^T bq
__device__ float g_qsum[D];              // column sums of Wq
__device__ float g_ksum[D];              // column sums of Wk
__device__ float g_scal[4];              // [0]=bq.bk  [1]=sum(bq)  [2]=sum(bk)
__device__ float g_Xq[BATCH * D];        // scaled last-row x
__device__ float g_s1[BATCH];            // u.xq + c
__device__ float g_s2[BATCH];            // qsum.xq + sum(bq)
__device__ float g_Y[BATCH * D];         // Xq@Abig + wv
__device__ float g_Z[BATCH * D];         // softmax-weighted x rows

// ---------------- kernel 1: small vector prep ----------------
__global__ void prep_vecs(const float* __restrict__ Wq, const float* __restrict__ bq,
                          const float* __restrict__ Wk, const float* __restrict__ bk) {
    int d = threadIdx.x;
    if (blockIdx.x == 0) {
        float su = 0.f, sq = 0.f;
        for (int e = 0; e < D; e++) {
            float w = Wq[e * D + d];
            su += w * bk[e];
            sq += w;
        }
        g_u[d] = su;
        g_qsum[d] = sq;
        int warp = d >> 5, lane = d & 31;
        if (warp < 3) {
            float a = 0.f;
            #pragma unroll
            for (int j = 0; j < 8; j++) {
                int e = lane + 32 * j;
                if (warp == 0) a += bq[e] * bk[e];
                else if (warp == 1) a += bq[e];
                else a += bk[e];
            }
            #pragma unroll
            for (int o = 16; o > 0; o >>= 1) a += __shfl_xor_sync(0xffffffffu, a, o);
            if (lane == 0) g_scal[warp] = a;
        }
    } else {
        float sw = 0.f, sk = 0.f;
        for (int e = 0; e < D; e++) {
            float w = Wk[e * D + d];
            sw += bq[e] * w;
            sk += w;
        }
        g_wv[d] = sw;
        g_ksum[d] = sk;
    }
}

// ---------------- kernel 2: Abig = Wq^T @ Wk (TN GEMM, 256^3) ----------------
__global__ void gemm_tn_abig(const float* __restrict__ Wq, const float* __restrict__ Wk) {
    __shared__ float As[16][64];
    __shared__ float Bs[16][64];
    int tid = threadIdx.x;
    int m0 = blockIdx.y * 64, n0 = blockIdx.x * 64;
    int tx = tid & 15, ty = tid >> 4;
    float acc[4][4] = {};
    int rr = (tid >> 6) * 4, cc = tid & 63;
    for (int k0 = 0; k0 < D; k0 += 16) {
        #pragma unroll
        for (int l = 0; l < 4; l++) {
            As[rr + l][cc] = Wq[(k0 + rr + l) * D + m0 + cc];
            Bs[rr + l][cc] = Wk[(k0 + rr + l) * D + n0 + cc];
        }
        __syncthreads();
        #pragma unroll
        for (int k = 0; k < 16; k++) {
            float4 a4 = *(const float4*)&As[k][ty * 4];
            float4 b4 = *(const float4*)&Bs[k][tx * 4];
            float av[4] = {a4.x, a4.y, a4.z, a4.w};
            float bv[4] = {b4.x, b4.y, b4.z, b4.w};
            #pragma unroll
            for (int i = 0; i < 4; i++)
                #pragma unroll
                for (int j = 0; j < 4; j++) acc[i][j] += av[i] * bv[j];
        }
        __syncthreads();
    }
    #pragma unroll
    for (int i = 0; i < 4; i++)
        #pragma unroll
        for (int j = 0; j < 4; j++)
            g_Abig[(m0 + ty * 4 + i) * D + n0 + tx * 4 + j] = acc[i][j];
}

// ---------------- kernel 3: gather scaled xq rows + per-batch scalars ----------------
__global__ void prep_xq(const float* __restrict__ x, const float* __restrict__ td) {
    int warp = threadIdx.x >> 5, lane = threadIdx.x & 31;
    int b = blockIdx.x * 8 + warp;
    float tdq = td[b * T + (T - 1)];
    const float* xr = x + ((size_t)b * T + (T - 1)) * D;
    float du = 0.f, dq = 0.f;
    #pragma unroll
    for (int j = 0; j < 8; j++) {
        int idx = lane + 32 * j;
        float v = xr[idx] * tdq;
        g_Xq[b * D + idx] = v;
        du += g_u[idx] * v;
        dq += g_qsum[idx] * v;
    }
    #pragma unroll
    for (int o = 16; o > 0; o >>= 1) {
        du += __shfl_xor_sync(0xffffffffu, du, o);
        dq += __shfl_xor_sync(0xffffffffu, dq, o);
    }
    if (lane == 0) {
        g_s1[b] = du + g_scal[0];   // u.xq + bq.bk
        g_s2[b] = dq + g_scal[1];   // qsum.xq + sum(bq)
    }
}

// ---------------- kernel 4: Y = Xq @ Abig + wv (NN GEMM, 2048x256x256) ----------------
__global__ void gemm_nn_y() {
    __shared__ float As[16][65];
    __shared__ float Bs[16][64];
    int tid = threadIdx.x;
    int m0 = blockIdx.y * 64, n0 = blockIdx.x * 64;
    int tx = tid & 15, ty = tid >> 4;
    float acc[4][4] = {};
    int rA = tid >> 4, cA = tid & 15;
    int rB = (tid >> 6) * 4, cB = tid & 63;
    for (int k0 = 0; k0 < D; k0 += 16) {
        #pragma unroll
        for (int l = 0; l < 4; l++) {
            As[cA][l * 16 + rA] = g_Xq[(m0 + l * 16 + rA) * D + k0 + cA];
            Bs[rB + l][cB] = g_Abig[(k0 + rB + l) * D + n0 + cB];
        }
        __syncthreads();
        #pragma unroll
        for (int k = 0; k < 16; k++) {
            float4 b4 = *(const float4*)&Bs[k][tx * 4];
            float bv[4] = {b4.x, b4.y, b4.z, b4.w};
            #pragma unroll
            for (int i = 0; i < 4; i++) {
                float a = As[k][ty * 4 + i];
                #pragma unroll
                for (int j = 0; j < 4; j++) acc[i][j] += a * bv[j];
            }
        }
        __syncthreads();
    }
    #pragma unroll
    for (int i = 0; i < 4; i++)
        #pragma unroll
        for (int j = 0; j < 4; j++)
            g_Y[(m0 + ty * 4 + i) * D + n0 + tx * 4 + j] = acc[i][j] + g_wv[n0 + tx * 4 + j];
}

// ---------------- kernel 5: per-batch scores + softmax + weighted x sum ----------------
__global__ void attn_kernel(const float* __restrict__ x, const int* __restrict__ mask,
                            const float* __restrict__ td) {
    extern __shared__ float sm[];
    float* smx  = sm;               // 50*256
    float* smY  = sm + T * D;       // 256
    float* smK  = smY + D;          // 256
    float* smtd = smK + D;          // 64
    float* smsc = smtd + 64;        // 64
    float* smw  = smsc + 64;        // 64
    int*   smm  = (int*)(smw + 64); // 64

    int b = blockIdx.x, tid = threadIdx.x;
    // load x tile (unscaled), vectorized
    const float4* xin = (const float4*)(x + (size_t)b * T * D);
    float4* smx4 = (float4*)smx;
    #pragma unroll
    for (int i = tid; i < T * D / 4; i += 256) smx4[i] = xin[i];
    smY[tid] = g_Y[b * D + tid];
    smK[tid] = g_ksum[tid];
    if (tid < T) {
        smtd[tid] = td[b * T + tid];
        smm[tid] = mask[b * T + tid];
    }
    __syncthreads();

    int mq = smm[T - 1];
    float s1b = g_s1[b], s2b = g_s2[b];
    float bksum = g_scal[2];
    int warp = tid >> 5, lane = tid & 31;

    for (int s = warp; s < T; s += 8) {
        const float* xr = smx + s * D;
        float dY = 0.f, dK = 0.f;
        #pragma unroll
        for (int j = 0; j < 8; j++) {
            float xv = xr[lane + 32 * j];
            dY += smY[lane + 32 * j] * xv;
            dK += smK[lane + 32 * j] * xv;
        }
        #pragma unroll
        for (int o = 16; o > 0; o >>= 1) {
            dY += __shfl_xor_sync(0xffffffffu, dY, o);
            dK += __shfl_xor_sync(0xffffffffu, dK, o);
        }
        if (lane == 0) {
            int ms = smm[s];
            float tds = smtd[s];
            float sc;
            if (mq) sc = ms ? (tds * dY + s1b) : (NEGC * s2b);
            else    sc = ms ? (NEGC * (tds * dK + bksum)) : (NEGC * NEGC * (float)D);
            smsc[s] = sc * INV_SQRT_D;
        }
    }
    __syncthreads();

    // softmax over T=50 (warp 0), fold in td so z = sum_s p_s * td_s * x_s
    if (warp == 0) {
        float v1 = (lane < T) ? smsc[lane] : -3.0e38f;
        float v2 = (lane + 32 < T) ? smsc[lane + 32] : -3.0e38f;
        float m = fmaxf(v1, v2);
        #pragma unroll
        for (int o = 16; o > 0; o >>= 1) m = fmaxf(m, __shfl_xor_sync(0xffffffffu, m, o));
        float e1 = (lane < T) ? expf(v1 - m) : 0.f;
        float e2 = (lane + 32 < T) ? expf(v2 - m) : 0.f;
        float es = e1 + e2;
        #pragma unroll
        for (int o = 16; o > 0; o >>= 1) es += __shfl_xor_sync(0xffffffffu, es, o);
        float inv = 1.0f / es;
        if (lane < T) smw[lane] = e1 * inv * smtd[lane];
        if (lane + 32 < T) smw[lane + 32] = e2 * inv * smtd[lane + 32];
    }
    __syncthreads();

    float acc = 0.f;
    #pragma unroll 10
    for (int s = 0; s < T; s++) acc += smw[s] * smx[s * D + tid];
    g_Z[b * D + tid] = acc;
}

// ---------------- kernel 6: Out = Z @ Wv^T + bv (NT GEMM, 2048x256x256) ----------------
__global__ void gemm_nt_out(const float* __restrict__ Wv, const float* __restrict__ bv,
                            float* __restrict__ out) {
    __shared__ float As[16][65];
    __shared__ float Bs[16][65];
    int tid = threadIdx.x;
    int m0 = blockIdx.y * 64, n0 = blockIdx.x * 64;
    int tx = tid & 15, ty = tid >> 4;
    float acc[4][4] = {};
    int rA = tid >> 4, cA = tid & 15;
    for (int k0 = 0; k0 < D; k0 += 16) {
        #pragma unroll
        for (int l = 0; l < 4; l++) {
            As[cA][l * 16 + rA] = g_Z[(m0 + l * 16 + rA) * D + k0 + cA];
            Bs[cA][l * 16 + rA] = Wv[(n0 + l * 16 + rA) * D + k0 + cA];
        }
        __syncthreads();
        #pragma unroll
        for (int k = 0; k < 16; k++) {
            #pragma unroll
            for (int i = 0; i < 4; i++) {
                float a = As[k][ty * 4 + i];
                #pragma unroll
                for (int j = 0; j < 4; j++) acc[i][j] += a * Bs[k][tx * 4 + j];
            }
        }
        __syncthreads();
    }
    #pragma unroll
    for (int i = 0; i < 4; i++)
        #pragma unroll
        for (int j = 0; j < 4; j++)
            out[(m0 + ty * 4 + i) * D + n0 + tx * 4 + j] = acc[i][j] + bv[n0 + tx * 4 + j];
}

// ---------------- launch ----------------
extern "C" void kernel_launch(void* const* d_in, const int* in_sizes, int n_in,
                              void* d_out, int out_size) {
    const float* x    = (const float*)d_in[0];
    const int*   mask = (const int*)d_in[1];
    const float* td   = (const float*)d_in[2];
    const float* Wq   = (const float*)d_in[3];
    const float* bq   = (const float*)d_in[4];
    const float* Wk   = (const float*)d_in[5];
    const float* bk   = (const float*)d_in[6];
    const float* Wv   = (const float*)d_in[7];
    const float* bv   = (const float*)d_in[8];
    float* out = (float*)d_out;

    const int attn_smem = (T * D + D + D + 64 + 64 + 64 + 64) * 4; // ~54.3 KB
    cudaFuncSetAttribute(attn_kernel, cudaFuncAttributeMaxDynamicSharedMemorySize, attn_smem);

    prep_vecs<<<2, 256>>>(Wq, bq, Wk, bk);
    gemm_tn_abig<<<dim3(4, 4), 256>>>(Wq, Wk);
    prep_xq<<<256, 256>>>(x, td);
    gemm_nn_y<<<dim3(4, 32), 256>>>();
    attn_kernel<<<BATCH, 256, attn_smem>>>(x, mask, td);
    gemm_nt_out<<<dim3(4, 32), 256>>>(Wv, bv, out);
}

// round 2
// speedup vs baseline: 1.0177x; 1.0177x over previous
#include <cuda_runtime.h>
#include <math.h>

#define BATCH 2048
#define T 50
#define D 256
#define NEGC (-100000.0f)
#define INV_SQRT_D 0.0625f

// ---------------- device scratch ----------------
__device__ float g_qv[BATCH * D];   // last-row q projection (incl. bias)
__device__ float g_Y[BATCH * D];    // qv @ Wk
__device__ float g_Z[BATCH * D];    // softmax-weighted scaled x rows
__device__ float g_ksum[D];         // column sums of Wk
__device__ float g_scal[1];         // sum(bk)

// ---------------- f32x2 packed-FMA helpers (Blackwell) ----------------
__device__ __forceinline__ void ffma2(unsigned long long& d, unsigned long long a,
                                      unsigned long long b) {
    asm("fma.rn.f32x2 %0, %1, %2, %0;" : "+l"(d) : "l"(a), "l"(b));
}
__device__ __forceinline__ float2 unpack2(unsigned long long v) {
    float2 r;
    asm("mov.b64 {%0, %1}, %2;" : "=f"(r.x), "=f"(r.y) : "l"(v));
    return r;
}

// ---------------- prep: ksum + sum(bk) ----------------
__global__ void prep_ksum(const float* __restrict__ Wk, const float* __restrict__ bk) {
    int d = threadIdx.x;
    float s = 0.f;
    #pragma unroll 8
    for (int e = 0; e < D; e++) s += Wk[e * D + d];
    g_ksum[d] = s;
    if (d < 32) {
        float a = 0.f;
        #pragma unroll
        for (int j = 0; j < 8; j++) a += bk[d + 32 * j];
        #pragma unroll
        for (int o = 16; o > 0; o >>= 1) a += __shfl_xor_sync(0xffffffffu, a, o);
        if (d == 0) g_scal[0] = a;
    }
}

// ---------------- unified 32x64-tile GEMM, f32x2 inner loop ----------------
// ASRC: 0 = x last rows * td   1 = g_qv   2 = g_Z
// BMODE: 0 = NN (B[k][n])      1 = NT (B[n][k])
// DST:  0 = g_qv   1 = g_Y   2 = Cout param
// BIAS: add bias[n]
template <int ASRC, int BMODE, int DST, int BIAS>
__global__ void gemm32x64(const float* __restrict__ x, const float* __restrict__ td,
                          const float* __restrict__ Bsrc, const float* __restrict__ bias,
                          float* __restrict__ Cout) {
    __shared__ float As2[32 * 66];  // A duplicated pairs: [k][2m],[k][2m+1]
    __shared__ float Bs[32 * 64];   // [k][n]
    int tid = threadIdx.x;
    int m0 = blockIdx.y * 32, n0 = blockIdx.x * 64;

    // A-load mapping: each thread owns one m-row, 4 consecutive k
    int am = tid >> 3;           // 0..31
    int ak = (tid & 7) * 4;      // 0..28
    const float* arow;
    float ascale = 1.0f;
    if (ASRC == 0) {
        int gb = m0 + am;
        arow = x + ((size_t)gb * T + (T - 1)) * D;
        ascale = td[gb * T + (T - 1)];
    } else if (ASRC == 1) {
        arow = g_qv + (size_t)(m0 + am) * D;
    } else {
        arow = g_Z + (size_t)(m0 + am) * D;
    }
    // B-load mappings
    int bkr = tid >> 3;          // NN: k row 0..31
    int bn8 = (tid & 7) * 8;     // NN: n offset
    int nB = tid >> 2;           // NT: 0..63
    int kc = (tid & 3) * 8;      // NT

    unsigned long long acc00 = 0, acc01 = 0, acc10 = 0, acc11 = 0;
    int tx = tid & 15, ty = tid >> 4;

    for (int k0 = 0; k0 < D; k0 += 32) {
        float4 av = *(const float4*)(arow + k0 + ak);
        float vv[4] = {av.x * ascale, av.y * ascale, av.z * ascale, av.w * ascale};
        #pragma unroll
        for (int i = 0; i < 4; i++) {
            As2[(ak + i) * 66 + 2 * am] = vv[i];
            As2[(ak + i) * 66 + 2 * am + 1] = vv[i];
        }
        if (BMODE == 0) {
            const float* bp = Bsrc + (size_t)(k0 + bkr) * D + n0 + bn8;
            float4 b1 = *(const float4*)bp;
            float4 b2 = *(const float4*)(bp + 4);
            *(float4*)&Bs[bkr * 64 + bn8] = b1;
            *(float4*)&Bs[bkr * 64 + bn8 + 4] = b2;
        } else {
            const float* bp = Bsrc + (size_t)(n0 + nB) * D + k0 + kc;
            float4 b1 = *(const float4*)bp;
            float4 b2 = *(const float4*)(bp + 4);
            Bs[(kc + 0) * 64 + nB] = b1.x;
            Bs[(kc + 1) * 64 + nB] = b1.y;
            Bs[(kc + 2) * 64 + nB] = b1.z;
            Bs[(kc + 3) * 64 + nB] = b1.w;
            Bs[(kc + 4) * 64 + nB] = b2.x;
            Bs[(kc + 5) * 64 + nB] = b2.y;
            Bs[(kc + 6) * 64 + nB] = b2.z;
            Bs[(kc + 7) * 64 + nB] = b2.w;
        }
        __syncthreads();
        #pragma unroll
        for (int k = 0; k < 32; k++) {
            unsigned long long a0 = *(const unsigned long long*)&As2[k * 66 + 4 * ty];
            unsigned long long a1 = *(const unsigned long long*)&As2[k * 66 + 4 * ty + 2];
            ulonglong2 bb = *(const ulonglong2*)&Bs[k * 64 + tx * 4];
            ffma2(acc00, a0, bb.x);
            ffma2(acc01, a0, bb.y);
            ffma2(acc10, a1, bb.x);
            ffma2(acc11, a1, bb.y);
        }
        __syncthreads();
    }

    float2 c00 = unpack2(acc00), c01 = unpack2(acc01);
    float2 c10 = unpack2(acc10), c11 = unpack2(acc11);
    int gn = n0 + tx * 4;
    float4 badd = make_float4(0.f, 0.f, 0.f, 0.f);
    if (BIAS) badd = *(const float4*)(bias + gn);
    float* C = (DST == 0) ? g_qv : (DST == 1) ? g_Y : Cout;
    int gm = m0 + 2 * ty;
    *(float4*)&C[(size_t)gm * D + gn] =
        make_float4(c00.x + badd.x, c00.y + badd.y, c01.x + badd.z, c01.y + badd.w);
    *(float4*)&C[(size_t)(gm + 1) * D + gn] =
        make_float4(c10.x + badd.x, c10.y + badd.y, c11.x + badd.z, c11.y + badd.w);
}

// ---------------- attn: scores + softmax + weighted x sum ----------------
__global__ void attn_kernel(const float* __restrict__ x, const int* __restrict__ mask,
                            const float* __restrict__ td, const float* __restrict__ bk) {
    extern __shared__ float sm[];
    float* smx = sm;                  // 50*256
    float* smV = sm + T * D;          // 256  (Y row if mq else ksum)
    float* smtd = smV + D;            // 64
    float* smDV = smtd + 64;          // 64
    float* smw = smDV + 64;           // 64
    int* smm = (int*)(smw + 64);      // 64

    int b = blockIdx.x, tid = threadIdx.x;
    int warp = tid >> 5, lane = tid & 31;

    int mq = mask[b * T + (T - 1)];
    const float4* xin = (const float4*)(x + (size_t)b * T * D);
    float4* smx4 = (float4*)smx;
    #pragma unroll
    for (int i = tid; i < T * D / 4; i += 256) smx4[i] = xin[i];
    smV[tid] = mq ? g_Y[b * D + tid] : g_ksum[tid];
    if (tid < T) {
        smtd[tid] = td[b * T + tid];
        smm[tid] = mask[b * T + tid];
    }
    __syncthreads();

    // warp 0: s1 = qv.bk, s2 = sum(qv) (kept in registers; warp 0 does softmax)
    float s1 = 0.f, s2 = 0.f;
    if (warp == 0) {
        const float4* q4 = (const float4*)(g_qv + (size_t)b * D);
        const float4* b4 = (const float4*)bk;
        float4 qa = q4[lane], qb = q4[lane + 32];
        float4 ba = b4[lane], bb = b4[lane + 32];
        s1 = qa.x * ba.x + qa.y * ba.y + qa.z * ba.z + qa.w * ba.w +
             qb.x * bb.x + qb.y * bb.y + qb.z * bb.z + qb.w * bb.w;
        s2 = qa.x + qa.y + qa.z + qa.w + qb.x + qb.y + qb.z + qb.w;
        #pragma unroll
        for (int o = 16; o > 0; o >>= 1) {
            s1 += __shfl_xor_sync(0xffffffffu, s1, o);
            s2 += __shfl_xor_sync(0xffffffffu, s2, o);
        }
    }

    // dots: one dot per key row (V = Y or ksum)
    const float4* v4 = (const float4*)smV;
    float4 va = v4[lane], vb = v4[lane + 32];
    for (int s = warp; s < T; s += 8) {
        const float4* xr = (const float4*)(smx + s * D);
        float4 x1 = xr[lane], x2 = xr[lane + 32];
        float dv = x1.x * va.x + x1.y * va.y + x1.z * va.z + x1.w * va.w +
                   x2.x * vb.x + x2.y * vb.y + x2.z * vb.z + x2.w * vb.w;
        #pragma unroll
        for (int o = 16; o > 0; o >>= 1) dv += __shfl_xor_sync(0xffffffffu, dv, o);
        if (lane == 0) smDV[s] = dv;
    }
    __syncthreads();

    // warp 0: final scores + softmax, weights folded with td
    if (warp == 0) {
        float bksum = g_scal[0];
        float v1 = -3.0e38f, v2 = -3.0e38f;
        if (lane < T) {
            int ms = smm[lane];
            float tds = smtd[lane];
            if (mq) v1 = ms ? (tds * smDV[lane] + s1) : (NEGC * s2);
            else    v1 = ms ? (NEGC * (tds * smDV[lane] + bksum)) : (NEGC * NEGC * (float)D);
            v1 *= INV_SQRT_D;
        }
        if (lane + 32 < T) {
            int s = lane + 32;
            int ms = smm[s];
            float tds = smtd[s];
            if (mq) v2 = ms ? (tds * smDV[s] + s1) : (NEGC * s2);
            else    v2 = ms ? (NEGC * (tds * smDV[s] + bksum)) : (NEGC * NEGC * (float)D);
            v2 *= INV_SQRT_D;
        }
        float m = fmaxf(v1, v2);
        #pragma unroll
        for (int o = 16; o > 0; o >>= 1) m = fmaxf(m, __shfl_xor_sync(0xffffffffu, m, o));
        float e1 = (lane < T) ? expf(v1 - m) : 0.f;
        float e2 = (lane + 32 < T) ? expf(v2 - m) : 0.f;
        float es = e1 + e2;
        #pragma unroll
        for (int o = 16; o > 0; o >>= 1) es += __shfl_xor_sync(0xffffffffu, es, o);
        float inv = 1.0f / es;
        if (lane < T) smw[lane] = e1 * inv * smtd[lane];
        if (lane + 32 < T) smw[lane + 32] = e2 * inv * smtd[lane + 32];
    }
    __syncthreads();

    float acc = 0.f;
    #pragma unroll 10
    for (int s = 0; s < T; s++) acc += smw[s] * smx[s * D + tid];
    g_Z[b * D + tid] = acc;
}

// ---------------- launch ----------------
extern "C" void kernel_launch(void* const* d_in, const int* in_sizes, int n_in,
                              void* d_out, int out_size) {
    const float* x = (const float*)d_in[0];
    const int* mask = (const int*)d_in[1];
    const float* td = (const float*)d_in[2];
    const float* Wq = (const float*)d_in[3];
    const float* bq = (const float*)d_in[4];
    const float* Wk = (const float*)d_in[5];
    const float* bk = (const float*)d_in[6];
    const float* Wv = (const float*)d_in[7];
    const float* bv = (const float*)d_in[8];
    float* out = (float*)d_out;

    const int attn_smem = (T * D + D + 64 + 64 + 64 + 64) * 4;  // ~53.5 KB
    cudaFuncSetAttribute(attn_kernel, cudaFuncAttributeMaxDynamicSharedMemorySize, attn_smem);

    dim3 gg(4, 64);
    prep_ksum<<<1, 256>>>(Wk, bk);
    gemm32x64<0, 1, 0, 1><<<gg, 256>>>(x, td, Wq, bq, nullptr);       // qv = xq*td @ Wq^T + bq
    gemm32x64<1, 0, 1, 0><<<gg, 256>>>(nullptr, nullptr, Wk, nullptr, nullptr);  // Y = qv @ Wk
    attn_kernel<<<BATCH, 256, attn_smem>>>(x, mask, td, bk);
    gemm32x64<2, 1, 2, 1><<<gg, 256>>>(nullptr, nullptr, Wv, bv, out);  // out = Z @ Wv^T + bv
}

// round 3
// speedup vs baseline: 1.3651x; 1.3413x over previous
#include <cuda_runtime.h>
#include <math.h>

#define BATCH 2048
#define T 50
#define D 256
#define NEGC (-100000.0f)
#define INV_SQRT_D 0.0625f

// ---------------- device scratch ----------------
__device__ float g_Aqk[D * D];      // Wq^T @ Wk   (Aqk[d][n] = sum_e Wq[e][d] Wk[e][n])
__device__ float g_u[D];            // sum_e bk[e] Wq[e][d]
__device__ float g_qrs[D];          // sum_e Wq[e][d]
__device__ float g_wv[D];           // sum_e bq[e] Wk[e][n]
__device__ float g_ksum[D];         // sum_e Wk[e][n]
__device__ float g_scal[3];         // [0]=bq.bk [1]=sum(bq) [2]=sum(bk)
__device__ float g_Y[BATCH * D];
__device__ float g_s1[BATCH];
__device__ float g_s2[BATCH];
__device__ float g_Z[BATCH * D];

// ---------------- f32x2 helpers ----------------
__device__ __forceinline__ void ffma2(unsigned long long& d, unsigned long long a,
                                      unsigned long long b) {
    asm("fma.rn.f32x2 %0, %1, %2, %0;" : "+l"(d) : "l"(a), "l"(b));
}
__device__ __forceinline__ float2 unpack2(unsigned long long v) {
    float2 r;
    asm("mov.b64 {%0, %1}, %2;" : "=f"(r.x), "=f"(r.y) : "l"(v));
    return r;
}
__device__ __forceinline__ float dot4(float4 a, float4 b) {
    return a.x * b.x + a.y * b.y + a.z * b.z + a.w * b.w;
}

// ---------------- K1: prep (Aqk + all small vectors), grid 16x16 ----------------
__global__ __launch_bounds__(256) void prep_kernel(const float* __restrict__ Wq,
                                                   const float* __restrict__ bq,
                                                   const float* __restrict__ Wk,
                                                   const float* __restrict__ bk) {
    __shared__ float Aw[32][16];   // Wq[e][m0+..]
    __shared__ float Bw[32][16];   // Wk[e][n0+..]
    __shared__ float s_bq[32], s_bk[32];
    int tid = threadIdx.x;
    int tx = tid & 15, ty = tid >> 4;
    int m0 = blockIdx.y * 16, n0 = blockIdx.x * 16;
    float acc = 0.f;
    float e0v = 0.f, e1v = 0.f;  // extras (u/qrs for bx==0, wv/ksum for by==0)
    bool do_u = (blockIdx.x == 0) && (ty == 0);
    bool do_w = (blockIdx.y == 0) && (ty == 1);

    for (int e0 = 0; e0 < D; e0 += 32) {
        #pragma unroll
        for (int i = 0; i < 2; i++) {
            int idx = tid + i * 256;
            int r = idx >> 4, c = idx & 15;
            Aw[r][c] = Wq[(e0 + r) * D + m0 + c];
            Bw[r][c] = Wk[(e0 + r) * D + n0 + c];
        }
        if (tid < 32) {
            s_bq[tid] = bq[e0 + tid];
            s_bk[tid] = bk[e0 + tid];
        }
        __syncthreads();
        #pragma unroll
        for (int e = 0; e < 32; e++) acc += Aw[e][ty] * Bw[e][tx];
        if (do_u) {
            #pragma unroll
            for (int e = 0; e < 32; e++) {
                float w = Aw[e][tx];
                e0v += s_bk[e] * w;
                e1v += w;
            }
        }
        if (do_w) {
            #pragma unroll
            for (int e = 0; e < 32; e++) {
                float w = Bw[e][tx];
                e0v += s_bq[e] * w;
                e1v += w;
            }
        }
        __syncthreads();
    }
    g_Aqk[(m0 + ty) * D + n0 + tx] = acc;
    if (do_u) { g_u[m0 + tx] = e0v; g_qrs[m0 + tx] = e1v; }
    if (do_w) { g_wv[n0 + tx] = e0v; g_ksum[n0 + tx] = e1v; }
    if (blockIdx.x == 0 && blockIdx.y == 0 && tid < 32) {
        float a0 = 0.f, a1 = 0.f, a2 = 0.f;
        #pragma unroll
        for (int j = 0; j < 8; j++) {
            int e = tid + 32 * j;
            float q = bq[e], k = bk[e];
            a0 += q * k; a1 += q; a2 += k;
        }
        #pragma unroll
        for (int o = 16; o > 0; o >>= 1) {
            a0 += __shfl_xor_sync(0xffffffffu, a0, o);
            a1 += __shfl_xor_sync(0xffffffffu, a1, o);
            a2 += __shfl_xor_sync(0xffffffffu, a2, o);
        }
        if (tid == 0) { g_scal[0] = a0; g_scal[1] = a1; g_scal[2] = a2; }
    }
}

// ---------------- K2: Y = (xq*td) @ Aqk + wv ; s1,s2 per row ----------------
__global__ __launch_bounds__(256) void gemm_y(const float* __restrict__ x,
                                              const float* __restrict__ td) {
    __shared__ float As2[32 * 66];
    __shared__ float Bs[32 * 64];
    int tid = threadIdx.x;
    int m0 = blockIdx.y * 32, n0 = blockIdx.x * 64;
    int am = tid >> 3, ak = (tid & 7) * 4;
    int gb = m0 + am;
    const float* arow = x + ((size_t)gb * T + (T - 1)) * D;
    float ascale = td[gb * T + (T - 1)];
    int bkr = tid >> 3, bn8 = (tid & 7) * 8;
    bool do_s = (blockIdx.x == 0);
    float du = 0.f, dq = 0.f;

    unsigned long long acc00 = 0, acc01 = 0, acc10 = 0, acc11 = 0;
    int tx = tid & 15, ty = tid >> 4;

    for (int k0 = 0; k0 < D; k0 += 32) {
        float4 av = *(const float4*)(arow + k0 + ak);
        float vv[4] = {av.x * ascale, av.y * ascale, av.z * ascale, av.w * ascale};
        #pragma unroll
        for (int i = 0; i < 4; i++) {
            As2[(ak + i) * 66 + 2 * am] = vv[i];
            As2[(ak + i) * 66 + 2 * am + 1] = vv[i];
        }
        if (do_s) {
            float4 u4 = *(const float4*)(g_u + k0 + ak);
            float4 q4 = *(const float4*)(g_qrs + k0 + ak);
            du += vv[0] * u4.x + vv[1] * u4.y + vv[2] * u4.z + vv[3] * u4.w;
            dq += vv[0] * q4.x + vv[1] * q4.y + vv[2] * q4.z + vv[3] * q4.w;
        }
        const float* bp = g_Aqk + (size_t)(k0 + bkr) * D + n0 + bn8;
        *(float4*)&Bs[bkr * 64 + bn8] = *(const float4*)bp;
        *(float4*)&Bs[bkr * 64 + bn8 + 4] = *(const float4*)(bp + 4);
        __syncthreads();
        #pragma unroll
        for (int k = 0; k < 32; k++) {
            unsigned long long a0 = *(const unsigned long long*)&As2[k * 66 + 4 * ty];
            unsigned long long a1 = *(const unsigned long long*)&As2[k * 66 + 4 * ty + 2];
            ulonglong2 bb = *(const ulonglong2*)&Bs[k * 64 + tx * 4];
            ffma2(acc00, a0, bb.x);
            ffma2(acc01, a0, bb.y);
            ffma2(acc10, a1, bb.x);
            ffma2(acc11, a1, bb.y);
        }
        __syncthreads();
    }
    if (do_s) {
        #pragma unroll
        for (int o = 4; o > 0; o >>= 1) {
            du += __shfl_xor_sync(0xffffffffu, du, o);
            dq += __shfl_xor_sync(0xffffffffu, dq, o);
        }
        if ((tid & 7) == 0) {
            g_s1[gb] = du + g_scal[0];
            g_s2[gb] = dq + g_scal[1];
        }
    }
    float2 c00 = unpack2(acc00), c01 = unpack2(acc01);
    float2 c10 = unpack2(acc10), c11 = unpack2(acc11);
    int gn = n0 + tx * 4;
    float4 w4 = *(const float4*)(g_wv + gn);
    int gm = m0 + 2 * ty;
    *(float4*)&g_Y[(size_t)gm * D + gn] =
        make_float4(c00.x + w4.x, c00.y + w4.y, c01.x + w4.z, c01.y + w4.w);
    *(float4*)&g_Y[(size_t)(gm + 1) * D + gn] =
        make_float4(c10.x + w4.x, c10.y + w4.y, c11.x + w4.z, c11.y + w4.w);
}

// ---------------- K3: attn ----------------
__global__ __launch_bounds__(256, 4) void attn_kernel(const float* __restrict__ x,
                                                      const int* __restrict__ mask,
                                                      const float* __restrict__ td) {
    extern __shared__ float sm[];
    float* smx = sm;                   // 50*256 floats (also reused for partials)
    float* smV = sm + T * D;           // 256
    float* smtd = smV + D;             // 64
    float* smDV = smtd + 64;           // 64
    float* smw = smDV + 64;            // 64
    int* smm = (int*)(smw + 64);       // 64

    int b = blockIdx.x, tid = threadIdx.x;
    int warp = tid >> 5, lane = tid & 31;

    int mq = __ldg(mask + b * T + (T - 1));
    smV[tid] = mq ? g_Y[(size_t)b * D + tid] : g_ksum[tid];
    if (tid < T) {
        smtd[tid] = td[b * T + tid];
        smm[tid] = mask[b * T + tid];
    }
    __syncthreads();

    // Phase A: load rows + dot from registers + stash to smem
    const float4* xin4 = (const float4*)(x + (size_t)b * T * D);
    float4* smx4 = (float4*)smx;
    float4 va = ((const float4*)smV)[lane];
    float4 vb = ((const float4*)smV)[lane + 32];
    for (int s = warp; s < T; s += 8) {
        float4 x1 = xin4[s * 64 + lane];
        float4 x2 = xin4[s * 64 + 32 + lane];
        smx4[s * 64 + lane] = x1;
        smx4[s * 64 + 32 + lane] = x2;
        float dv = dot4(x1, va) + dot4(x2, vb);
        #pragma unroll
        for (int o = 16; o > 0; o >>= 1) dv += __shfl_xor_sync(0xffffffffu, dv, o);
        if (lane == 0) smDV[s] = dv;
    }
    __syncthreads();

    // Phase B: softmax (warp 0)
    if (warp == 0) {
        float s1b = g_s1[b], s2b = g_s2[b], bksum = g_scal[2];
        float v1 = -3.0e38f, v2 = -3.0e38f;
        if (lane < T) {
            int ms = smm[lane];
            float tds = smtd[lane];
            if (mq) v1 = ms ? (tds * smDV[lane] + s1b) : (NEGC * s2b);
            else    v1 = ms ? (NEGC * (tds * smDV[lane] + bksum)) : (NEGC * NEGC * (float)D);
            v1 *= INV_SQRT_D;
        }
        if (lane + 32 < T) {
            int s = lane + 32;
            int ms = smm[s];
            float tds = smtd[s];
            if (mq) v2 = ms ? (tds * smDV[s] + s1b) : (NEGC * s2b);
            else    v2 = ms ? (NEGC * (tds * smDV[s] + bksum)) : (NEGC * NEGC * (float)D);
            v2 *= INV_SQRT_D;
        }
        float m = fmaxf(v1, v2);
        #pragma unroll
        for (int o = 16; o > 0; o >>= 1) m = fmaxf(m, __shfl_xor_sync(0xffffffffu, m, o));
        float e1 = (lane < T) ? expf(v1 - m) : 0.f;
        float e2 = (lane + 32 < T) ? expf(v2 - m) : 0.f;
        float es = e1 + e2;
        #pragma unroll
        for (int o = 16; o > 0; o >>= 1) es += __shfl_xor_sync(0xffffffffu, es, o);
        float inv = 1.0f / es;
        if (lane < T) smw[lane] = e1 * inv * smtd[lane];
        if (lane + 32 < T) smw[lane + 32] = e2 * inv * smtd[lane + 32];
    }
    __syncthreads();

    // Phase C: weighted sum, float4 column-quads, 4 row-groups
    int g = tid >> 6, q = tid & 63;
    float4 acc = make_float4(0.f, 0.f, 0.f, 0.f);
    for (int s = g; s < T; s += 4) {
        float w = smw[s];
        float4 xv = smx4[s * 64 + q];
        acc.x += w * xv.x; acc.y += w * xv.y; acc.z += w * xv.z; acc.w += w * xv.w;
    }
    __syncthreads();                    // everyone done reading smx
    smx4[g * 64 + q] = acc;             // partials overlay smx
    __syncthreads();
    if (tid < 64) {
        float4 p0 = smx4[tid], p1 = smx4[64 + tid];
        float4 p2 = smx4[128 + tid], p3 = smx4[192 + tid];
        float4 r = make_float4(p0.x + p1.x + p2.x + p3.x, p0.y + p1.y + p2.y + p3.y,
                               p0.z + p1.z + p2.z + p3.z, p0.w + p1.w + p2.w + p3.w);
        ((float4*)(g_Z + (size_t)b * D))[tid] = r;
    }
}

// ---------------- K4: out = Z @ Wv^T + bv ----------------
__global__ __launch_bounds__(256) void gemm_out(const float* __restrict__ Wv,
                                                const float* __restrict__ bv,
                                                float* __restrict__ out) {
    __shared__ float As2[32 * 66];
    __shared__ float Bs[32 * 64];
    int tid = threadIdx.x;
    int m0 = blockIdx.y * 32, n0 = blockIdx.x * 64;
    int am = tid >> 3, ak = (tid & 7) * 4;
    const float* arow = g_Z + (size_t)(m0 + am) * D;
    int nB = tid >> 2, kc = (tid & 3) * 8;

    unsigned long long acc00 = 0, acc01 = 0, acc10 = 0, acc11 = 0;
    int tx = tid & 15, ty = tid >> 4;

    for (int k0 = 0; k0 < D; k0 += 32) {
        float4 av = *(const float4*)(arow + k0 + ak);
        #pragma unroll
        for (int i = 0; i < 4; i++) {
            float v = (i == 0) ? av.x : (i == 1) ? av.y : (i == 2) ? av.z : av.w;
            As2[(ak + i) * 66 + 2 * am] = v;
            As2[(ak + i) * 66 + 2 * am + 1] = v;
        }
        const float* bp = Wv + (size_t)(n0 + nB) * D + k0 + kc;
        float4 b1 = *(const float4*)bp;
        float4 b2 = *(const float4*)(bp + 4);
        Bs[(kc + 0) * 64 + nB] = b1.x;
        Bs[(kc + 1) * 64 + nB] = b1.y;
        Bs[(kc + 2) * 64 + nB] = b1.z;
        Bs[(kc + 3) * 64 + nB] = b1.w;
        Bs[(kc + 4) * 64 + nB] = b2.x;
        Bs[(kc + 5) * 64 + nB] = b2.y;
        Bs[(kc + 6) * 64 + nB] = b2.z;
        Bs[(kc + 7) * 64 + nB] = b2.w;
        __syncthreads();
        #pragma unroll
        for (int k = 0; k < 32; k++) {
            unsigned long long a0 = *(const unsigned long long*)&As2[k * 66 + 4 * ty];
            unsigned long long a1 = *(const unsigned long long*)&As2[k * 66 + 4 * ty + 2];
            ulonglong2 bb = *(const ulonglong2*)&Bs[k * 64 + tx * 4];
            ffma2(acc00, a0, bb.x);
            ffma2(acc01, a0, bb.y);
            ffma2(acc10, a1, bb.x);
            ffma2(acc11, a1, bb.y);
        }
        __syncthreads();
    }
    float2 c00 = unpack2(acc00), c01 = unpack2(acc01);
    float2 c10 = unpack2(acc10), c11 = unpack2(acc11);
    int gn = n0 + tx * 4;
    float4 b4 = *(const float4*)(bv + gn);
    int gm = m0 + 2 * ty;
    *(float4*)&out[(size_t)gm * D + gn] =
        make_float4(c00.x + b4.x, c00.y + b4.y, c01.x + b4.z, c01.y + b4.w);
    *(float4*)&out[(size_t)(gm + 1) * D + gn] =
        make_float4(c10.x + b4.x, c10.y + b4.y, c11.x + b4.z, c11.y + b4.w);
}

// ---------------- launch ----------------
extern "C" void kernel_launch(void* const* d_in, const int* in_sizes, int n_in,
                              void* d_out, int out_size) {
    const float* x = (const float*)d_in[0];
    const int* mask = (const int*)d_in[1];
    const float* td = (const float*)d_in[2];
    const float* Wq = (const float*)d_in[3];
    const float* bq = (const float*)d_in[4];
    const float* Wk = (const float*)d_in[5];
    const float* bk = (const float*)d_in[6];
    const float* Wv = (const float*)d_in[7];
    const float* bv = (const float*)d_in[8];
    float* out = (float*)d_out;

    const int attn_smem = (T * D + D + 64 + 64 + 64 + 64) * 4;  // 53.25 KB
    cudaFuncSetAttribute(attn_kernel, cudaFuncAttributeMaxDynamicSharedMemorySize, attn_smem);

    prep_kernel<<<dim3(16, 16), 256>>>(Wq, bq, Wk, bk);
    gemm_y<<<dim3(4, 64), 256>>>(x, td);
    attn_kernel<<<BATCH, 256, attn_smem>>>(x, mask, td);
    gemm_out<<<dim3(4, 64), 256>>>(Wv, bv, out);
}

// round 4
// speedup vs baseline: 1.5006x; 1.0993x over previous
#include <cuda_runtime.h>
#include <math.h>

#define BATCH 2048
#define T 50
#define D 256
#define NEGC (-100000.0f)
#define INV_SQRT_D 0.0625f

// ---------------- device scratch ----------------
__device__ float g_Aqk[D * D];      // Wq^T @ Wk
__device__ float g_u[D];            // sum_e bk[e] Wq[e][d]
__device__ float g_qrs[D];          // sum_e Wq[e][d]
__device__ float g_wv[D];           // sum_e bq[e] Wk[e][n]
__device__ float g_ksum[D];         // sum_e Wk[e][n]
__device__ float g_scal[3];         // [0]=bq.bk [1]=sum(bq) [2]=sum(bk)
__device__ float g_Y[BATCH * D];
__device__ float g_s1[BATCH];
__device__ float g_s2[BATCH];
__device__ float g_Z[BATCH * D];

// ---------------- f32x2 helpers ----------------
__device__ __forceinline__ void ffma2(unsigned long long& d, unsigned long long a,
                                      unsigned long long b) {
    asm("fma.rn.f32x2 %0, %1, %2, %0;" : "+l"(d) : "l"(a), "l"(b));
}
__device__ __forceinline__ float2 unpack2(unsigned long long v) {
    float2 r;
    asm("mov.b64 {%0, %1}, %2;" : "=f"(r.x), "=f"(r.y) : "l"(v));
    return r;
}
__device__ __forceinline__ unsigned long long pack_dup(float v) {
    unsigned long long r;
    asm("mov.b64 %0, {%1, %1};" : "=l"(r) : "f"(v));
    return r;
}
__device__ __forceinline__ float dot4(float4 a, float4 b) {
    return a.x * b.x + a.y * b.y + a.z * b.z + a.w * b.w;
}

#define AS_STRIDE 132  // floats per k-row of duplicated-A tile (mult of 4, 528B)

// ---------------- K1: prep (Aqk + small vectors), grid 16x16 ----------------
__global__ __launch_bounds__(256) void prep_kernel(const float* __restrict__ Wq,
                                                   const float* __restrict__ bq,
                                                   const float* __restrict__ Wk,
                                                   const float* __restrict__ bk) {
    __shared__ float Aw[32][16];
    __shared__ float Bw[32][16];
    __shared__ float s_bq[32], s_bk[32];
    int tid = threadIdx.x;
    int tx = tid & 15, ty = tid >> 4;
    int m0 = blockIdx.y * 16, n0 = blockIdx.x * 16;
    float acc = 0.f;
    float e0v = 0.f, e1v = 0.f;
    bool do_u = (blockIdx.x == 0) && (ty == 0);
    bool do_w = (blockIdx.y == 0) && (ty == 1);

    for (int e0 = 0; e0 < D; e0 += 32) {
        #pragma unroll
        for (int i = 0; i < 2; i++) {
            int idx = tid + i * 256;
            int r = idx >> 4, c = idx & 15;
            Aw[r][c] = Wq[(e0 + r) * D + m0 + c];
            Bw[r][c] = Wk[(e0 + r) * D + n0 + c];
        }
        if (tid < 32) {
            s_bq[tid] = bq[e0 + tid];
            s_bk[tid] = bk[e0 + tid];
        }
        __syncthreads();
        #pragma unroll
        for (int e = 0; e < 32; e++) acc += Aw[e][ty] * Bw[e][tx];
        if (do_u) {
            #pragma unroll
            for (int e = 0; e < 32; e++) {
                float w = Aw[e][tx];
                e0v += s_bk[e] * w;
                e1v += w;
            }
        }
        if (do_w) {
            #pragma unroll
            for (int e = 0; e < 32; e++) {
                float w = Bw[e][tx];
                e0v += s_bq[e] * w;
                e1v += w;
            }
        }
        __syncthreads();
    }
    g_Aqk[(m0 + ty) * D + n0 + tx] = acc;
    if (do_u) { g_u[m0 + tx] = e0v; g_qrs[m0 + tx] = e1v; }
    if (do_w) { g_wv[n0 + tx] = e0v; g_ksum[n0 + tx] = e1v; }
    if (blockIdx.x == 0 && blockIdx.y == 0 && tid < 32) {
        float a0 = 0.f, a1 = 0.f, a2 = 0.f;
        #pragma unroll
        for (int j = 0; j < 8; j++) {
            int e = tid + 32 * j;
            float q = bq[e], k = bk[e];
            a0 += q * k; a1 += q; a2 += k;
        }
        #pragma unroll
        for (int o = 16; o > 0; o >>= 1) {
            a0 += __shfl_xor_sync(0xffffffffu, a0, o);
            a1 += __shfl_xor_sync(0xffffffffu, a1, o);
            a2 += __shfl_xor_sync(0xffffffffu, a2, o);
        }
        if (tid == 0) { g_scal[0] = a0; g_scal[1] = a1; g_scal[2] = a2; }
    }
}

// ---------------- K2: Y = (xq*td) @ Aqk + wv ; s1,s2 ----------------
// 64x64 tile, BK=32, thread tile 4m x 4n via f32x2.
__global__ __launch_bounds__(256) void gemm_y(const float* __restrict__ x,
                                              const float* __restrict__ td) {
    __shared__ float As2[32 * AS_STRIDE];  // duplicated pairs, [k][2m]
    __shared__ float Bs[32 * 64];          // [k][n]
    __shared__ float sdu[256], sdq[256];
    int tid = threadIdx.x;
    int m0 = blockIdx.y * 64, n0 = blockIdx.x * 64;
    int tx = tid & 15, ty = tid >> 4;

    // A mapping: row am (0..63), k-chunk ak (0,8,16,24)
    int am = tid & 63, ak = (tid >> 6) * 8;
    int gb = m0 + am;
    const float* arow = x + ((size_t)gb * T + (T - 1)) * D;
    float ascale = td[gb * T + (T - 1)];
    // B mapping (NN): k-row bkr (0..31), n-chunk bn8
    int bkr = tid >> 3, bn8 = (tid & 7) * 8;
    bool do_s = (blockIdx.x == 0);
    float du = 0.f, dq = 0.f;

    unsigned long long acc00 = 0, acc01 = 0, acc10 = 0, acc11 = 0;
    unsigned long long acc20 = 0, acc21 = 0, acc30 = 0, acc31 = 0;

    float4 aL = *(const float4*)(arow + ak);
    float4 aH = *(const float4*)(arow + ak + 4);
    const float* bp0 = g_Aqk + (size_t)bkr * D + n0 + bn8;
    float4 bL = *(const float4*)bp0;
    float4 bH = *(const float4*)(bp0 + 4);

    for (int k0 = 0; k0 < D; k0 += 32) {
        float av[8] = {aL.x, aL.y, aL.z, aL.w, aH.x, aH.y, aH.z, aH.w};
        __syncthreads();
        unsigned long long* As2u = (unsigned long long*)As2;
        #pragma unroll
        for (int i = 0; i < 8; i++) {
            float v = av[i] * ascale;
            As2u[(ak + i) * (AS_STRIDE / 2) + am] = pack_dup(v);
        }
        *(float4*)&Bs[bkr * 64 + bn8] = bL;
        *(float4*)&Bs[bkr * 64 + bn8 + 4] = bH;
        if (do_s) {
            float4 u4a = *(const float4*)(g_u + k0 + ak);
            float4 u4b = *(const float4*)(g_u + k0 + ak + 4);
            float4 q4a = *(const float4*)(g_qrs + k0 + ak);
            float4 q4b = *(const float4*)(g_qrs + k0 + ak + 4);
            float uu[8] = {u4a.x, u4a.y, u4a.z, u4a.w, u4b.x, u4b.y, u4b.z, u4b.w};
            float qq[8] = {q4a.x, q4a.y, q4a.z, q4a.w, q4b.x, q4b.y, q4b.z, q4b.w};
            #pragma unroll
            for (int i = 0; i < 8; i++) {
                float v = av[i] * ascale;
                du += v * uu[i];
                dq += v * qq[i];
            }
        }
        __syncthreads();
        if (k0 + 32 < D) {
            aL = *(const float4*)(arow + k0 + 32 + ak);
            aH = *(const float4*)(arow + k0 + 32 + ak + 4);
            const float* bp = g_Aqk + (size_t)(k0 + 32 + bkr) * D + n0 + bn8;
            bL = *(const float4*)bp;
            bH = *(const float4*)(bp + 4);
        }
        #pragma unroll
        for (int k = 0; k < 32; k++) {
            ulonglong2 aA = *(const ulonglong2*)&As2[k * AS_STRIDE + 8 * ty];
            ulonglong2 aB = *(const ulonglong2*)&As2[k * AS_STRIDE + 8 * ty + 4];
            ulonglong2 bb = *(const ulonglong2*)&Bs[k * 64 + tx * 4];
            ffma2(acc00, aA.x, bb.x); ffma2(acc01, aA.x, bb.y);
            ffma2(acc10, aA.y, bb.x); ffma2(acc11, aA.y, bb.y);
            ffma2(acc20, aB.x, bb.x); ffma2(acc21, aB.x, bb.y);
            ffma2(acc30, aB.y, bb.x); ffma2(acc31, aB.y, bb.y);
        }
    }

    if (do_s) {
        sdu[tid] = du;
        sdq[tid] = dq;
        __syncthreads();
        if (tid < 64) {
            float tdu = sdu[tid] + sdu[tid + 64] + sdu[tid + 128] + sdu[tid + 192];
            float tdq = sdq[tid] + sdq[tid + 64] + sdq[tid + 128] + sdq[tid + 192];
            g_s1[m0 + tid] = tdu + g_scal[0];
            g_s2[m0 + tid] = tdq + g_scal[1];
        }
    }

    int gn = n0 + tx * 4;
    float4 w4 = *(const float4*)(g_wv + gn);
    unsigned long long accs[4][2] = {{acc00, acc01}, {acc10, acc11},
                                     {acc20, acc21}, {acc30, acc31}};
    #pragma unroll
    for (int i = 0; i < 4; i++) {
        float2 lo = unpack2(accs[i][0]), hi = unpack2(accs[i][1]);
        int gm = m0 + 4 * ty + i;
        *(float4*)&g_Y[(size_t)gm * D + gn] =
            make_float4(lo.x + w4.x, lo.y + w4.y, hi.x + w4.z, hi.y + w4.w);
    }
}

// ---------------- K3: attn (unchanged from round 3) ----------------
__global__ __launch_bounds__(256, 4) void attn_kernel(const float* __restrict__ x,
                                                      const int* __restrict__ mask,
                                                      const float* __restrict__ td) {
    extern __shared__ float sm[];
    float* smx = sm;
    float* smV = sm + T * D;
    float* smtd = smV + D;
    float* smDV = smtd + 64;
    float* smw = smDV + 64;
    int* smm = (int*)(smw + 64);

    int b = blockIdx.x, tid = threadIdx.x;
    int warp = tid >> 5, lane = tid & 31;

    int mq = __ldg(mask + b * T + (T - 1));
    smV[tid] = mq ? g_Y[(size_t)b * D + tid] : g_ksum[tid];
    if (tid < T) {
        smtd[tid] = td[b * T + tid];
        smm[tid] = mask[b * T + tid];
    }
    __syncthreads();

    const float4* xin4 = (const float4*)(x + (size_t)b * T * D);
    float4* smx4 = (float4*)smx;
    float4 va = ((const float4*)smV)[lane];
    float4 vb = ((const float4*)smV)[lane + 32];
    for (int s = warp; s < T; s += 8) {
        float4 x1 = xin4[s * 64 + lane];
        float4 x2 = xin4[s * 64 + 32 + lane];
        smx4[s * 64 + lane] = x1;
        smx4[s * 64 + 32 + lane] = x2;
        float dv = dot4(x1, va) + dot4(x2, vb);
        #pragma unroll
        for (int o = 16; o > 0; o >>= 1) dv += __shfl_xor_sync(0xffffffffu, dv, o);
        if (lane == 0) smDV[s] = dv;
    }
    __syncthreads();

    if (warp == 0) {
        float s1b = g_s1[b], s2b = g_s2[b], bksum = g_scal[2];
        float v1 = -3.0e38f, v2 = -3.0e38f;
        if (lane < T) {
            int ms = smm[lane];
            float tds = smtd[lane];
            if (mq) v1 = ms ? (tds * smDV[lane] + s1b) : (NEGC * s2b);
            else    v1 = ms ? (NEGC * (tds * smDV[lane] + bksum)) : (NEGC * NEGC * (float)D);
            v1 *= INV_SQRT_D;
        }
        if (lane + 32 < T) {
            int s = lane + 32;
            int ms = smm[s];
            float tds = smtd[s];
            if (mq) v2 = ms ? (tds * smDV[s] + s1b) : (NEGC * s2b);
            else    v2 = ms ? (NEGC * (tds * smDV[s] + bksum)) : (NEGC * NEGC * (float)D);
            v2 *= INV_SQRT_D;
        }
        float m = fmaxf(v1, v2);
        #pragma unroll
        for (int o = 16; o > 0; o >>= 1) m = fmaxf(m, __shfl_xor_sync(0xffffffffu, m, o));
        float e1 = (lane < T) ? expf(v1 - m) : 0.f;
        float e2 = (lane + 32 < T) ? expf(v2 - m) : 0.f;
        float es = e1 + e2;
        #pragma unroll
        for (int o = 16; o > 0; o >>= 1) es += __shfl_xor_sync(0xffffffffu, es, o);
        float inv = 1.0f / es;
        if (lane < T) smw[lane] = e1 * inv * smtd[lane];
        if (lane + 32 < T) smw[lane + 32] = e2 * inv * smtd[lane + 32];
    }
    __syncthreads();

    int g = tid >> 6, q = tid & 63;
    float4 acc = make_float4(0.f, 0.f, 0.f, 0.f);
    for (int s = g; s < T; s += 4) {
        float w = smw[s];
        float4 xv = smx4[s * 64 + q];
        acc.x += w * xv.x; acc.y += w * xv.y; acc.z += w * xv.z; acc.w += w * xv.w;
    }
    __syncthreads();
    smx4[g * 64 + q] = acc;
    __syncthreads();
    if (tid < 64) {
        float4 p0 = smx4[tid], p1 = smx4[64 + tid];
        float4 p2 = smx4[128 + tid], p3 = smx4[192 + tid];
        float4 r = make_float4(p0.x + p1.x + p2.x + p3.x, p0.y + p1.y + p2.y + p3.y,
                               p0.z + p1.z + p2.z + p3.z, p0.w + p1.w + p2.w + p3.w);
        ((float4*)(g_Z + (size_t)b * D))[tid] = r;
    }
}

// ---------------- K4: out = Z @ Wv^T + bv ----------------
__global__ __launch_bounds__(256) void gemm_out(const float* __restrict__ Wv,
                                                const float* __restrict__ bv,
                                                float* __restrict__ out) {
    __shared__ float As2[32 * AS_STRIDE];
    __shared__ float Bs[32 * 64];
    int tid = threadIdx.x;
    int m0 = blockIdx.y * 64, n0 = blockIdx.x * 64;
    int tx = tid & 15, ty = tid >> 4;

    int am = tid & 63, ak = (tid >> 6) * 8;
    const float* arow = g_Z + (size_t)(m0 + am) * D;
    // B (NT): row nB (0..63) of Wv, k-chunk kc
    int nB = tid & 63, kc = (tid >> 6) * 8;
    const float* brow = Wv + (size_t)(n0 + nB) * D;

    unsigned long long acc00 = 0, acc01 = 0, acc10 = 0, acc11 = 0;
    unsigned long long acc20 = 0, acc21 = 0, acc30 = 0, acc31 = 0;

    float4 aL = *(const float4*)(arow + ak);
    float4 aH = *(const float4*)(arow + ak + 4);
    float4 bL = *(const float4*)(brow + kc);
    float4 bH = *(const float4*)(brow + kc + 4);

    for (int k0 = 0; k0 < D; k0 += 32) {
        float av[8] = {aL.x, aL.y, aL.z, aL.w, aH.x, aH.y, aH.z, aH.w};
        float bvv[8] = {bL.x, bL.y, bL.z, bL.w, bH.x, bH.y, bH.z, bH.w};
        __syncthreads();
        unsigned long long* As2u = (unsigned long long*)As2;
        #pragma unroll
        for (int i = 0; i < 8; i++)
            As2u[(ak + i) * (AS_STRIDE / 2) + am] = pack_dup(av[i]);
        #pragma unroll
        for (int i = 0; i < 8; i++)
            Bs[(kc + i) * 64 + nB] = bvv[i];
        __syncthreads();
        if (k0 + 32 < D) {
            aL = *(const float4*)(arow + k0 + 32 + ak);
            aH = *(const float4*)(arow + k0 + 32 + ak + 4);
            bL = *(const float4*)(brow + k0 + 32 + kc);
            bH = *(const float4*)(brow + k0 + 32 + kc + 4);
        }
        #pragma unroll
        for (int k = 0; k < 32; k++) {
            ulonglong2 aA = *(const ulonglong2*)&As2[k * AS_STRIDE + 8 * ty];
            ulonglong2 aB = *(const ulonglong2*)&As2[k * AS_STRIDE + 8 * ty + 4];
            ulonglong2 bb = *(const ulonglong2*)&Bs[k * 64 + tx * 4];
            ffma2(acc00, aA.x, bb.x); ffma2(acc01, aA.x, bb.y);
            ffma2(acc10, aA.y, bb.x); ffma2(acc11, aA.y, bb.y);
            ffma2(acc20, aB.x, bb.x); ffma2(acc21, aB.x, bb.y);
            ffma2(acc30, aB.y, bb.x); ffma2(acc31, aB.y, bb.y);
        }
    }

    int gn = n0 + tx * 4;
    float4 b4 = *(const float4*)(bv + gn);
    unsigned long long accs[4][2] = {{acc00, acc01}, {acc10, acc11},
                                     {acc20, acc21}, {acc30, acc31}};
    #pragma unroll
    for (int i = 0; i < 4; i++) {
        float2 lo = unpack2(accs[i][0]), hi = unpack2(accs[i][1]);
        int gm = m0 + 4 * ty + i;
        *(float4*)&out[(size_t)gm * D + gn] =
            make_float4(lo.x + b4.x, lo.y + b4.y, hi.x + b4.z, hi.y + b4.w);
    }
}

// ---------------- launch ----------------
extern "C" void kernel_launch(void* const* d_in, const int* in_sizes, int n_in,
                              void* d_out, int out_size) {
    const float* x = (const float*)d_in[0];
    const int* mask = (const int*)d_in[1];
    const float* td = (const float*)d_in[2];
    const float* Wq = (const float*)d_in[3];
    const float* bq = (const float*)d_in[4];
    const float* Wk = (const float*)d_in[5];
    const float* bk = (const float*)d_in[6];
    const float* Wv = (const float*)d_in[7];
    const float* bv = (const float*)d_in[8];
    float* out = (float*)d_out;

    const int attn_smem = (T * D + D + 64 + 64 + 64 + 64) * 4;  // 53.25 KB
    cudaFuncSetAttribute(attn_kernel, cudaFuncAttributeMaxDynamicSharedMemorySize, attn_smem);

    prep_kernel<<<dim3(16, 16), 256>>>(Wq, bq, Wk, bk);
    gemm_y<<<dim3(4, 32), 256>>>(x, td);
    attn_kernel<<<BATCH, 256, attn_smem>>>(x, mask, td);
    gemm_out<<<dim3(4, 32), 256>>>(Wv, bv, out);
}